// round 1
// baseline (speedup 1.0000x reference)
#include <cuda_runtime.h>
#include <cstdint>

#define N_GENOMES 30000
#define N_GENES   240000
#define N_SAMPLES 128
#define N_SEQS    80000

// One warp per gene. Each lane owns 4 samples (32 lanes * 4 = 128).
// G = A[g] + 1 - pos*B[g]; out[seq] += exp(G) via vector reduction atomics.
__global__ void __launch_bounds__(256) gene_segsum_kernel(
    const float* __restrict__ A,
    const float* __restrict__ B,
    const float* __restrict__ pos,
    const int*   __restrict__ genome_idx,
    const int*   __restrict__ seq_idx,
    float*       __restrict__ out)
{
    const int warp = (blockIdx.x * blockDim.x + threadIdx.x) >> 5;
    const int lane = threadIdx.x & 31;
    if (warp >= N_GENES) return;

    const int   gi = __ldg(genome_idx + warp);
    const int   si = __ldg(seq_idx + warp);
    const float p  = __ldg(pos + warp);

    const float4 a = *reinterpret_cast<const float4*>(A + (size_t)gi * N_SAMPLES + lane * 4);
    const float4 b = *reinterpret_cast<const float4*>(B + (size_t)gi * N_SAMPLES + lane * 4);

    float4 v;
    v.x = __expf(fmaf(-p, b.x, a.x) + 1.0f);
    v.y = __expf(fmaf(-p, b.y, a.y) + 1.0f);
    v.z = __expf(fmaf(-p, b.z, a.z) + 1.0f);
    v.w = __expf(fmaf(-p, b.w, a.w) + 1.0f);

    float* dst = out + (size_t)si * N_SAMPLES + lane * 4;
    asm volatile("red.global.add.v4.f32 [%0], {%1, %2, %3, %4};"
                 :: "l"(dst), "f"(v.x), "f"(v.y), "f"(v.z), "f"(v.w)
                 : "memory");
}

extern "C" void kernel_launch(void* const* d_in, const int* in_sizes, int n_in,
                              void* d_out, int out_size)
{
    const float* A          = (const float*)d_in[0];
    const float* B          = (const float*)d_in[1];
    const float* pos        = (const float*)d_in[2];
    const int*   genome_idx = (const int*)d_in[3];
    const int*   seq_idx    = (const int*)d_in[4];
    float*       out        = (float*)d_out;

    // Output is poisoned; segment-sum needs zeros. Memset is graph-capturable.
    cudaMemsetAsync(out, 0, (size_t)out_size * sizeof(float), 0);

    // 8 warps (8 genes) per 256-thread block.
    const int warps_per_block = 8;
    const int blocks = (N_GENES + warps_per_block - 1) / warps_per_block;
    gene_segsum_kernel<<<blocks, 256>>>(A, B, pos, genome_idx, seq_idx, out);
}